// round 7
// baseline (speedup 1.0000x reference)
#include <cuda_runtime.h>
#include <cstdint>

#define NMAX 100000
#define EMAX 1000000
#define DIM 64

// ---------------- scratch (static device globals; no allocation) ----------------
__device__ __align__(16) float g_h[NMAX * DIM];      // layer-1 output, pre-scaled by norm_out
__device__ int   g_deg_out[NMAX];
__device__ int   g_deg_in[NMAX];
__device__ float g_norm_out[NMAX];
__device__ float g_norm_in[NMAX];
__device__ int   g_row_start[NMAX];
__device__ int   g_cursor[NMAX];
__device__ int   g_esrc[EMAX];
__device__ int   g_total;

// ---------------- K1: zero degree counters + global cursor ----------------
__global__ void zero_deg_kernel(int n_nodes) {
    int i = blockIdx.x * blockDim.x + threadIdx.x;
    if (i < n_nodes) { g_deg_out[i] = 0; g_deg_in[i] = 0; }
    if (i == 0) g_total = 0;
}

// ---------------- K2: degree histogram, 4 edges/thread (MLP=4 REDs) ----------
__global__ void __launch_bounds__(256) degree_kernel(
    const int* __restrict__ src, const int* __restrict__ dst, int n_edges)
{
    int t = blockIdx.x * blockDim.x + threadIdx.x;
    int e0 = t * 4;
    if (e0 + 4 <= n_edges) {
        int4 s4 = *reinterpret_cast<const int4*>(src + e0);
        int4 d4 = *reinterpret_cast<const int4*>(dst + e0);
        atomicAdd(&g_deg_out[s4.x], 1);
        atomicAdd(&g_deg_out[s4.y], 1);
        atomicAdd(&g_deg_out[s4.z], 1);
        atomicAdd(&g_deg_out[s4.w], 1);
        atomicAdd(&g_deg_in[d4.x], 1);
        atomicAdd(&g_deg_in[d4.y], 1);
        atomicAdd(&g_deg_in[d4.z], 1);
        atomicAdd(&g_deg_in[d4.w], 1);
    } else {
        for (int e = e0; e < n_edges; e++) {
            atomicAdd(&g_deg_out[src[e]], 1);
            atomicAdd(&g_deg_in[dst[e]], 1);
        }
    }
}

// ---------------- K3: block-scan row allocation (order-free) + norms ----------
__global__ void __launch_bounds__(256) rowalloc_kernel(int n_nodes) {
    int t = threadIdx.x;
    int base = blockIdx.x * 1024;

    int d[4]; int local = 0;
#pragma unroll
    for (int j = 0; j < 4; j++) {
        int idx = base + t * 4 + j;
        d[j] = (idx < n_nodes) ? g_deg_in[idx] : 0;
        local += d[j];
    }
    int lane = t & 31, w = t >> 5;
    int s = local;
    for (int o = 1; o < 32; o <<= 1) {
        int x = __shfl_up_sync(~0u, s, o);
        if (lane >= o) s += x;
    }
    __shared__ int wsum[8];
    __shared__ int s_off;
    if (lane == 31) wsum[w] = s;
    __syncthreads();
    if (w == 0 && lane < 8) {
        int x = wsum[lane];
        for (int o = 1; o < 8; o <<= 1) {
            int y = __shfl_up_sync(0xffu, x, o);
            if (lane >= o) x += y;
        }
        wsum[lane] = x;
    }
    __syncthreads();
    if (t == 0) s_off = atomicAdd(&g_total, wsum[7]);
    __syncthreads();

    int excl = s - local + (w > 0 ? wsum[w - 1] : 0) + s_off;
#pragma unroll
    for (int j = 0; j < 4; j++) {
        int idx = base + t * 4 + j;
        if (idx < n_nodes) {
            g_row_start[idx] = excl;
            g_cursor[idx]    = excl;
            g_norm_in[idx]   = rsqrtf(fmaxf((float)d[j], 1.0f));
            g_norm_out[idx]  = rsqrtf(fmaxf((float)g_deg_out[idx], 1.0f));
        }
        excl += d[j];
    }
}

// ---------------- K4: CSR fill, 4 edges/thread (MLP=4 atomic chains) ----------
__global__ void __launch_bounds__(256) csrfill_kernel(
    const int* __restrict__ src, const int* __restrict__ dst, int n_edges)
{
    int t = blockIdx.x * blockDim.x + threadIdx.x;
    int e0 = t * 4;
    if (e0 + 4 <= n_edges) {
        int4 s4 = *reinterpret_cast<const int4*>(src + e0);
        int4 d4 = *reinterpret_cast<const int4*>(dst + e0);
        int p0 = atomicAdd(&g_cursor[d4.x], 1);
        int p1 = atomicAdd(&g_cursor[d4.y], 1);
        int p2 = atomicAdd(&g_cursor[d4.z], 1);
        int p3 = atomicAdd(&g_cursor[d4.w], 1);
        g_esrc[p0] = s4.x;
        g_esrc[p1] = s4.y;
        g_esrc[p2] = s4.z;
        g_esrc[p3] = s4.w;
    } else {
        for (int e = e0; e < n_edges; e++) {
            int pos = atomicAdd(&g_cursor[dst[e]], 1);
            g_esrc[pos] = src[e];
        }
    }
}

// ---------------- K5/K6: fused gather + dense layer -----------------------
// Per block: gather 96 node rows directly into sA (with norm_in applied),
// then out = act(sA @ W + b). Gather main loop is 8-wide for MLP=8.
template <bool FIRST>
__global__ void __launch_bounds__(192) fused_layer_kernel(
    const float* __restrict__ feat,
    const float* __restrict__ W, const float* __restrict__ bias,
    float* __restrict__ out, int n_nodes)
{
    __shared__ float sW[DIM * DIM];       // 16 KB
    __shared__ float sb[DIM];
    __shared__ float sA[96][DIM + 1];     // ~25 KB

    int tid = threadIdx.x;

    for (int i = tid; i < DIM * DIM / 4; i += 192)
        reinterpret_cast<float4*>(sW)[i] = reinterpret_cast<const float4*>(W)[i];
    if (tid < DIM / 4)
        reinterpret_cast<float4*>(sb)[tid] = reinterpret_cast<const float4*>(bias)[tid];

    int node0 = blockIdx.x * 96;
    const float4* f4 = FIRST ? reinterpret_cast<const float4*>(feat)
                             : reinterpret_cast<const float4*>(g_h);

    // ---- gather stage: 1536 (node, quad) tasks over 192 threads ----
    for (int i = tid; i < 96 * 16; i += 192) {
        int r = i >> 4, q = i & 15;
        int node = node0 + r;
        float4 a0 = make_float4(0.f, 0.f, 0.f, 0.f);
        float4 a1 = make_float4(0.f, 0.f, 0.f, 0.f);
        float4 a2 = make_float4(0.f, 0.f, 0.f, 0.f);
        float4 a3 = make_float4(0.f, 0.f, 0.f, 0.f);
        float ni = 0.f;
        if (node < n_nodes) {
            ni = __ldg(&g_norm_in[node]);
            int beg = __ldg(&g_row_start[node]);
            int end = beg + __ldg(&g_deg_in[node]);
            int e = beg;
            // 8-wide: 8 independent row loads in flight
            for (; e + 8 <= end; e += 8) {
                int sidx[8];
#pragma unroll
                for (int j = 0; j < 8; j++) sidx[j] = __ldg(&g_esrc[e + j]);
                float4 v[8];
#pragma unroll
                for (int j = 0; j < 8; j++) v[j] = __ldg(f4 + (size_t)sidx[j] * 16 + q);
                if (FIRST) {
#pragma unroll
                    for (int j = 0; j < 8; j++) {
                        float n = __ldg(&g_norm_out[sidx[j]]);
                        v[j].x *= n; v[j].y *= n; v[j].z *= n; v[j].w *= n;
                    }
                }
                a0.x += v[0].x + v[4].x; a0.y += v[0].y + v[4].y;
                a0.z += v[0].z + v[4].z; a0.w += v[0].w + v[4].w;
                a1.x += v[1].x + v[5].x; a1.y += v[1].y + v[5].y;
                a1.z += v[1].z + v[5].z; a1.w += v[1].w + v[5].w;
                a2.x += v[2].x + v[6].x; a2.y += v[2].y + v[6].y;
                a2.z += v[2].z + v[6].z; a2.w += v[2].w + v[6].w;
                a3.x += v[3].x + v[7].x; a3.y += v[3].y + v[7].y;
                a3.z += v[3].z + v[7].z; a3.w += v[3].w + v[7].w;
            }
            // 4-wide tail
            if (e + 4 <= end) {
                int sidx[4];
#pragma unroll
                for (int j = 0; j < 4; j++) sidx[j] = __ldg(&g_esrc[e + j]);
                float4 v[4];
#pragma unroll
                for (int j = 0; j < 4; j++) v[j] = __ldg(f4 + (size_t)sidx[j] * 16 + q);
                if (FIRST) {
#pragma unroll
                    for (int j = 0; j < 4; j++) {
                        float n = __ldg(&g_norm_out[sidx[j]]);
                        v[j].x *= n; v[j].y *= n; v[j].z *= n; v[j].w *= n;
                    }
                }
                a0.x += v[0].x; a0.y += v[0].y; a0.z += v[0].z; a0.w += v[0].w;
                a1.x += v[1].x; a1.y += v[1].y; a1.z += v[1].z; a1.w += v[1].w;
                a2.x += v[2].x; a2.y += v[2].y; a2.z += v[2].z; a2.w += v[2].w;
                a3.x += v[3].x; a3.y += v[3].y; a3.z += v[3].z; a3.w += v[3].w;
                e += 4;
            }
            // 2-wide tail
            if (e + 2 <= end) {
                int s0 = __ldg(&g_esrc[e]);
                int s1 = __ldg(&g_esrc[e + 1]);
                float4 v0 = __ldg(f4 + (size_t)s0 * 16 + q);
                float4 v1 = __ldg(f4 + (size_t)s1 * 16 + q);
                if (FIRST) {
                    float n0 = __ldg(&g_norm_out[s0]);
                    float n1 = __ldg(&g_norm_out[s1]);
                    v0.x *= n0; v0.y *= n0; v0.z *= n0; v0.w *= n0;
                    v1.x *= n1; v1.y *= n1; v1.z *= n1; v1.w *= n1;
                }
                a0.x += v0.x; a0.y += v0.y; a0.z += v0.z; a0.w += v0.w;
                a1.x += v1.x; a1.y += v1.y; a1.z += v1.z; a1.w += v1.w;
                e += 2;
            }
            // last edge
            if (e < end) {
                int s0 = __ldg(&g_esrc[e]);
                float4 v0 = __ldg(f4 + (size_t)s0 * 16 + q);
                if (FIRST) {
                    float n0 = __ldg(&g_norm_out[s0]);
                    v0.x *= n0; v0.y *= n0; v0.z *= n0; v0.w *= n0;
                }
                a0.x += v0.x; a0.y += v0.y; a0.z += v0.z; a0.w += v0.w;
            }
        }
        sA[r][q * 4 + 0] = (a0.x + a1.x + a2.x + a3.x) * ni;
        sA[r][q * 4 + 1] = (a0.y + a1.y + a2.y + a3.y) * ni;
        sA[r][q * 4 + 2] = (a0.z + a1.z + a2.z + a3.z) * ni;
        sA[r][q * 4 + 3] = (a0.w + a1.w + a2.w + a3.w) * ni;
    }
    __syncthreads();

    // ---- dense stage: each thread 8 nodes x 4 cols ----
    int cg = tid & 15;
    int ng = tid >> 4;

    float4 acc[8];
#pragma unroll
    for (int i = 0; i < 8; i++) acc[i] = make_float4(0.f, 0.f, 0.f, 0.f);

    const float4* sW4 = reinterpret_cast<const float4*>(sW);
#pragma unroll 8
    for (int k = 0; k < DIM; k++) {
        float4 w = sW4[k * 16 + cg];
#pragma unroll
        for (int i = 0; i < 8; i++) {
            float a = sA[ng * 8 + i][k];
            acc[i].x = fmaf(a, w.x, acc[i].x);
            acc[i].y = fmaf(a, w.y, acc[i].y);
            acc[i].z = fmaf(a, w.z, acc[i].z);
            acc[i].w = fmaf(a, w.w, acc[i].w);
        }
    }

    float4 bb = reinterpret_cast<const float4*>(sb)[cg];
#pragma unroll
    for (int i = 0; i < 8; i++) {
        int node = node0 + ng * 8 + i;
        if (node >= n_nodes) break;
        float4 y;
        y.x = acc[i].x + bb.x;
        y.y = acc[i].y + bb.y;
        y.z = acc[i].z + bb.z;
        y.w = acc[i].w + bb.w;
        if (FIRST) {
            float sc = g_norm_out[node];   // pre-scale for layer-2 gather
            y.x = fmaxf(y.x, 0.f) * sc;
            y.y = fmaxf(y.y, 0.f) * sc;
            y.z = fmaxf(y.z, 0.f) * sc;
            y.w = fmaxf(y.w, 0.f) * sc;
            reinterpret_cast<float4*>(g_h)[(size_t)node * 16 + cg] = y;
        } else {
            reinterpret_cast<float4*>(out)[(size_t)node * 16 + cg] = y;
        }
    }
}

// ---------------- launch ----------------
extern "C" void kernel_launch(void* const* d_in, const int* in_sizes, int n_in,
                              void* d_out, int out_size)
{
    const int*   src = (const int*)d_in[0];
    const int*   dst = (const int*)d_in[1];
    const float* x   = (const float*)d_in[2];
    const float* W1  = (const float*)d_in[3];
    const float* b1  = (const float*)d_in[4];
    const float* W2  = (const float*)d_in[5];
    const float* b2  = (const float*)d_in[6];

    int E = in_sizes[0];
    int N = in_sizes[2] / DIM;
    if (N > NMAX) N = NMAX;
    if (E > EMAX) E = EMAX;

    int ethreads4 = (E + 3) / 4;

    zero_deg_kernel<<<(N + 255) / 256, 256>>>(N);
    degree_kernel<<<(ethreads4 + 255) / 256, 256>>>(src, dst, E);
    rowalloc_kernel<<<(N + 1023) / 1024, 256>>>(N);
    csrfill_kernel<<<(ethreads4 + 255) / 256, 256>>>(src, dst, E);

    fused_layer_kernel<true><<<(N + 95) / 96, 192>>>(x, W1, b1, nullptr, N);
    fused_layer_kernel<false><<<(N + 95) / 96, 192>>>(nullptr, W2, b2, (float*)d_out, N);
}